// round 10
// baseline (speedup 1.0000x reference)
#include <cuda_runtime.h>
#include <math.h>

#define BB   8
#define NN   2048
#define KDIN 300
#define DD   96
#define MTOT (BB*NN)   // 16384

// ---------------- scratch (no runtime allocation allowed) ----------------
__device__ __align__(128) float g_h [3][MTOT][DD];
__device__ __align__(128) float g_ap[3][3][MTOT][DD];  // [ksplit][branch] msg partials
__device__ __align__(128) float g_t [3][MTOT][DD];

// ---------------- f32x2 helpers ----------------
__device__ __forceinline__ unsigned long long pack2(float x, float y) {
    unsigned long long r;
    asm("mov.b64 %0, {%1,%2};" : "=l"(r) : "f"(x), "f"(y));
    return r;
}
__device__ __forceinline__ float2 unpack2(unsigned long long v) {
    float2 f;
    asm("mov.b64 {%0,%1}, %2;" : "=f"(f.x), "=f"(f.y) : "l"(v));
    return f;
}
__device__ __forceinline__ void ffma2(unsigned long long& acc, unsigned long long a, unsigned long long b) {
    asm("fma.rn.f32x2 %0, %1, %2, %0;" : "+l"(acc) : "l"(a), "l"(b));
}
__device__ __forceinline__ void cpa16(void* s, const void* g) {
    unsigned su = (unsigned)__cvta_generic_to_shared(s);
    asm volatile("cp.async.cg.shared.global [%0], [%1], 16;" :: "r"(su), "l"(g));
}
__device__ __forceinline__ float sigmoidf_(float x) { return 1.f / (1.f + expf(-x)); }
__device__ __forceinline__ float lrelu(float v)     { return v > 0.f ? v : 0.2f * v; }

// =========================================================================
//  ENCODE: h_i = mask_i * relu(x @ W_enc[i] + b_enc[i])
// =========================================================================
__device__ __forceinline__ void step32_64(const float Xs[64][32], const float Ws[32][96],
                                          int tx, int ty, unsigned long long acc[4][3])
{
    #pragma unroll
    for (int k = 0; k < 32; k++) {
        unsigned long long bp[3];
        #pragma unroll
        for (int q = 0; q < 3; q++)
            bp[q] = *(const unsigned long long*)&Ws[k][tx*6 + 2*q];
        #pragma unroll
        for (int i = 0; i < 4; i++) {
            float a = Xs[ty*4 + i][k];
            unsigned long long ap = pack2(a, a);
            #pragma unroll
            for (int q = 0; q < 3; q++) ffma2(acc[i][q], ap, bp[q]);
        }
    }
}

__global__ __launch_bounds__(256) void encode_kernel(
    const float* __restrict__ x, const float* __restrict__ Wenc, const float* __restrict__ benc,
    const float* __restrict__ mk0, const float* __restrict__ mk1, const float* __restrict__ mk2)
{
    __shared__ __align__(16) float Xs[64][32];
    __shared__ __align__(16) float Ws[32][96];
    int br = blockIdx.y;
    int m0 = blockIdx.x * 64;
    const float* mask = (br == 0) ? mk0 : ((br == 1) ? mk1 : mk2);
    const float* W = Wenc + (size_t)br * KDIN * DD;
    int tid = threadIdx.x, tx = tid & 15, ty = tid >> 4;
    unsigned long long acc[4][3] = {};
    #pragma unroll 1
    for (int k0 = 0; k0 < 320; k0 += 32) {
        #pragma unroll
        for (int l = 0; l < 8; l++) {
            int e = tid + l*256;
            int r = e >> 5, k = e & 31;
            int kk = k0 + k;
            Xs[r][k] = (kk < KDIN) ? x[(size_t)(m0 + r)*KDIN + kk] : 0.f;
        }
        #pragma unroll
        for (int l = 0; l < 12; l++) {
            int e = tid + l*256;
            int kk = e / 96, d = e % 96;
            int kg = k0 + kk;
            Ws[kk][d] = (kg < KDIN) ? W[(size_t)kg*DD + d] : 0.f;
        }
        __syncthreads();
        step32_64(Xs, Ws, tx, ty, acc);
        __syncthreads();
    }
    #pragma unroll
    for (int i = 0; i < 4; i++) {
        int m = m0 + ty*4 + i;
        float mkv = mask[m];
        #pragma unroll
        for (int q = 0; q < 3; q++) {
            float2 v = unpack2(acc[i][q]);
            int c = tx*6 + 2*q;
            float o0 = fmaxf(v.x + benc[br*DD + c],     0.f) * mkv;
            float o1 = fmaxf(v.y + benc[br*DD + c + 1], 0.f) * mkv;
            *(float2*)&g_h[br][m][c] = make_float2(o0, o1);
        }
    }
}

// =========================================================================
//  MESSAGE PASSING v3: a = adj @ h
//  - A operand straight from global (register float4 per row, L1-broadcast)
//  - Hs double-buffered in smem via cp.async
//  - 256 thr, 128-row x 96-col tile, K split in 3 (672/672/704)
// =========================================================================
__global__ __launch_bounds__(256, 2) void msg_kernel(
    const float* __restrict__ adjA, const float* __restrict__ adjB, const float* __restrict__ adjC)
{
    __shared__ __align__(16) float Hs[2][32][96];
    int br = blockIdx.z / 3, kz = blockIdx.z % 3;
    int b  = blockIdx.y;
    int n0 = blockIdx.x * 128;
    int kbeg = (kz == 0) ? 0   : ((kz == 1) ? 672  : 1344);
    int kend = (kz == 0) ? 672 : ((kz == 1) ? 1344 : 2048);
    int nch  = (kend - kbeg) >> 5;                         // 21 or 22 chunks of 32
    const float* adj = ((br == 0) ? adjA : ((br == 1) ? adjB : adjC)) + (size_t)b * NN * NN;
    const float* H   = &g_h[br][b * NN][0];
    float* Ao = &g_ap[kz][br][b * NN][0];
    int tid = threadIdx.x, tx = tid & 15, ty = tid >> 4;   // ty 0..15, 8 rows each
    const float* aBase = adj + (size_t)(n0 + ty*8) * NN + kbeg;

    unsigned long long acc[8][3] = {};

    // prologue: async-load chunk 0
    {
        const float* Hc = H + (size_t)kbeg * DD;
        #pragma unroll
        for (int l = 0; l < 3; l++) {
            int e = tid + l*256; int kk = e / 24, d4 = e % 24;
            cpa16(&Hs[0][kk][d4*4], Hc + (size_t)kk*DD + d4*4);
        }
        asm volatile("cp.async.commit_group;");
    }

    #pragma unroll 1
    for (int c = 0; c < nch; c++) {
        if (c + 1 < nch) {
            const float* Hc = H + (size_t)(kbeg + (c+1)*32) * DD;
            float* dst = &Hs[(c+1) & 1][0][0];
            #pragma unroll
            for (int l = 0; l < 3; l++) {
                int e = tid + l*256; int kk = e / 24, d4 = e % 24;
                cpa16(dst + kk*96 + d4*4, Hc + (size_t)kk*DD + d4*4);
            }
            asm volatile("cp.async.commit_group;");
            asm volatile("cp.async.wait_group 1;");
        } else {
            asm volatile("cp.async.wait_group 0;");
        }
        __syncthreads();

        const float (*Hb)[96] = Hs[c & 1];
        const float* aPtr = aBase + c*32;
        #pragma unroll
        for (int k4 = 0; k4 < 8; k4++) {
            float4 av[8];
            #pragma unroll
            for (int i = 0; i < 8; i++)
                av[i] = *(const float4*)(aPtr + (size_t)i*NN + k4*4);
            if (k4 == 0 && c + 1 < nch) {
                #pragma unroll
                for (int i = 0; i < 8; i++)
                    asm volatile("prefetch.global.L1 [%0];" :: "l"(aPtr + (size_t)i*NN + 32));
            }
            #pragma unroll
            for (int kk = 0; kk < 4; kk++) {
                unsigned long long bp0 = *(const unsigned long long*)&Hb[k4*4 + kk][tx*6 + 0];
                unsigned long long bp1 = *(const unsigned long long*)&Hb[k4*4 + kk][tx*6 + 2];
                unsigned long long bp2 = *(const unsigned long long*)&Hb[k4*4 + kk][tx*6 + 4];
                #pragma unroll
                for (int i = 0; i < 8; i++) {
                    float a = (kk == 0) ? av[i].x : (kk == 1) ? av[i].y : (kk == 2) ? av[i].z : av[i].w;
                    unsigned long long ap = pack2(a, a);
                    ffma2(acc[i][0], ap, bp0);
                    ffma2(acc[i][1], ap, bp1);
                    ffma2(acc[i][2], ap, bp2);
                }
            }
        }
        __syncthreads();
    }

    #pragma unroll
    for (int i = 0; i < 8; i++) {
        int n = n0 + ty*8 + i;
        #pragma unroll
        for (int q = 0; q < 3; q++) {
            float2 v = unpack2(acc[i][q]);
            *(float2*)&Ao[(size_t)n*DD + tx*6 + 2*q] = v;
        }
    }
}

// =========================================================================
//  FUSED GRU GATES (R8, loader now sums 3 msg partials)
// =========================================================================
#define GATES_SMEM ((64*96 + 64*96 + 32*96) * 4)

__device__ __forceinline__ void gemm96s(const float (*X)[96], float (*w_s)[96],
                                        const float* __restrict__ W,
                                        int tid, int tx, int ty,
                                        unsigned long long acc[4][3])
{
    #pragma unroll 1
    for (int c = 0; c < 3; c++) {
        __syncthreads();
        #pragma unroll
        for (int l = 0; l < 3; l++) {
            int e = tid + l*256;
            int kk = e / 24, d4 = e % 24;
            *(float4*)&w_s[kk][d4*4] = *(const float4*)(W + (size_t)(c*32 + kk)*DD + d4*4);
        }
        __syncthreads();
        #pragma unroll
        for (int k2 = 0; k2 < 16; k2++) {
            float2 av[4];
            #pragma unroll
            for (int i = 0; i < 4; i++)
                av[i] = *(const float2*)&X[ty*4 + i][c*32 + k2*2];
            #pragma unroll
            for (int kk = 0; kk < 2; kk++) {
                unsigned long long bp[3];
                #pragma unroll
                for (int q = 0; q < 3; q++)
                    bp[q] = *(const unsigned long long*)&w_s[k2*2 + kk][tx*6 + 2*q];
                #pragma unroll
                for (int i = 0; i < 4; i++) {
                    float a = kk ? av[i].y : av[i].x;
                    unsigned long long ap = pack2(a, a);
                    #pragma unroll
                    for (int q = 0; q < 3; q++) ffma2(acc[i][q], ap, bp[q]);
                }
            }
        }
    }
}

__global__ __launch_bounds__(256, 2) void gates_kernel(
    const float* __restrict__ Wgru, const float* __restrict__ bgru,
    const float* __restrict__ mk0, const float* __restrict__ mk1, const float* __restrict__ mk2)
{
    extern __shared__ float dsm[];
    float (*a_s)[96] = (float(*)[96])dsm;
    float (*h_s)[96] = (float(*)[96])(dsm + 64*96);
    float (*w_s)[96] = (float(*)[96])(dsm + 2*64*96);

    int br = blockIdx.y;
    int m0 = blockIdx.x * 64;
    const float* mask = (br == 0) ? mk0 : ((br == 1) ? mk1 : mk2);
    const float* Wb = Wgru + (size_t)(br*6) * DD * DD;
    const float* bb = bgru + (size_t)(br*6) * DD;
    int tid = threadIdx.x, tx = tid & 15, ty = tid >> 4;

    // load a = sum of 3 msg K-partials, and h
    #pragma unroll
    for (int l = 0; l < 6; l++) {
        int e = tid + l*256;
        int r = e / 24, d4 = e % 24;
        float4 u  = *(const float4*)&g_ap[0][br][m0 + r][d4*4];
        float4 v  = *(const float4*)&g_ap[1][br][m0 + r][d4*4];
        float4 w2 = *(const float4*)&g_ap[2][br][m0 + r][d4*4];
        float4 w;
        w.x = u.x + v.x + w2.x; w.y = u.y + v.y + w2.y;
        w.z = u.z + v.z + w2.z; w.w = u.w + v.w + w2.w;
        *(float4*)&a_s[r][d4*4] = w;
        *(float4*)&h_s[r][d4*4] = *(const float4*)&g_h[br][m0 + r][d4*4];
    }

    unsigned long long acc[4][3];

    // ---- z ----
    #pragma unroll
    for (int i=0;i<4;i++) for (int q=0;q<3;q++) acc[i][q]=0ull;
    gemm96s(a_s, w_s, Wb + 0*DD*DD, tid, tx, ty, acc);
    gemm96s(h_s, w_s, Wb + 1*DD*DD, tid, tx, ty, acc);
    float2 zr[4][3];
    #pragma unroll
    for (int i = 0; i < 4; i++)
        #pragma unroll
        for (int q = 0; q < 3; q++) {
            float2 v = unpack2(acc[i][q]);
            int c = tx*6 + 2*q;
            zr[i][q].x = sigmoidf_(v.x + bb[0*DD + c]     + bb[1*DD + c]);
            zr[i][q].y = sigmoidf_(v.y + bb[0*DD + c + 1] + bb[1*DD + c + 1]);
        }

    // ---- hp = a@Wh0 ----
    #pragma unroll
    for (int i=0;i<4;i++) for (int q=0;q<3;q++) acc[i][q]=0ull;
    gemm96s(a_s, w_s, Wb + 4*DD*DD, tid, tx, ty, acc);
    float2 hp[4][3];
    #pragma unroll
    for (int i=0;i<4;i++) for (int q=0;q<3;q++) hp[i][q] = unpack2(acc[i][q]);

    // ---- r; rh = r*h -> a_s ----
    #pragma unroll
    for (int i=0;i<4;i++) for (int q=0;q<3;q++) acc[i][q]=0ull;
    gemm96s(a_s, w_s, Wb + 2*DD*DD, tid, tx, ty, acc);
    gemm96s(h_s, w_s, Wb + 3*DD*DD, tid, tx, ty, acc);
    __syncthreads();
    #pragma unroll
    for (int i = 0; i < 4; i++)
        #pragma unroll
        for (int q = 0; q < 3; q++) {
            float2 v = unpack2(acc[i][q]);
            int c = tx*6 + 2*q;
            float2 hv = *(const float2*)&h_s[ty*4 + i][c];
            float r0 = sigmoidf_(v.x + bb[2*DD + c]     + bb[3*DD + c]);
            float r1 = sigmoidf_(v.y + bb[2*DD + c + 1] + bb[3*DD + c + 1]);
            *(float2*)&a_s[ty*4 + i][c] = make_float2(r0*hv.x, r1*hv.y);
        }

    // ---- hh_part = rh@Wh1 ----
    #pragma unroll
    for (int i=0;i<4;i++) for (int q=0;q<3;q++) acc[i][q]=0ull;
    gemm96s(a_s, w_s, Wb + 5*DD*DD, tid, tx, ty, acc);

    // ---- blend ----
    #pragma unroll
    for (int i = 0; i < 4; i++) {
        int m = m0 + ty*4 + i;
        float mkv = mask[m];
        #pragma unroll
        for (int q = 0; q < 3; q++) {
            float2 v = unpack2(acc[i][q]);
            int c = tx*6 + 2*q;
            float2 hv = *(const float2*)&h_s[ty*4 + i][c];
            float hh0 = fmaxf(mkv * (v.x + hp[i][q].x + bb[4*DD + c]     + bb[5*DD + c]),     0.f);
            float hh1 = fmaxf(mkv * (v.y + hp[i][q].y + bb[4*DD + c + 1] + bb[5*DD + c + 1]), 0.f);
            float o0 = hh0*zr[i][q].x + hv.x*(1.f - zr[i][q].x);
            float o1 = hh1*zr[i][q].y + hv.y*(1.f - zr[i][q].y);
            *(float2*)&g_h[br][m][c] = make_float2(o0, o1);
        }
    }
}

// =========================================================================
//  f1 / f2
// =========================================================================
__device__ __forceinline__ void mm96(const float* __restrict__ In, const float* __restrict__ W,
                                     int m0, int tid, unsigned long long acc[4][3])
{
    __shared__ __align__(16) float Xs[64][32];
    __shared__ __align__(16) float Ws[32][96];
    int tx = tid & 15, ty = tid >> 4;
    #pragma unroll 1
    for (int k0 = 0; k0 < DD; k0 += 32) {
        #pragma unroll
        for (int l = 0; l < 2; l++) {
            int e = tid + l*256;
            int r = e >> 3, k4 = e & 7;
            *(float4*)&Xs[r][k4*4] = *(const float4*)(In + (size_t)(m0 + r)*DD + k0 + k4*4);
        }
        #pragma unroll
        for (int l = 0; l < 3; l++) {
            int e = tid + l*256;
            int kk = e / 24, d4 = e % 24;
            *(float4*)&Ws[kk][d4*4] = *(const float4*)(W + (size_t)(k0 + kk)*DD + d4*4);
        }
        __syncthreads();
        step32_64(Xs, Ws, tx, ty, acc);
        __syncthreads();
    }
}

__device__ __forceinline__ void mm96pairL(const float* __restrict__ T0, const float* __restrict__ T1,
                                          const float* __restrict__ W, int m0, int tid,
                                          unsigned long long acc[4][3])
{
    __shared__ __align__(16) float Xs[64][32];
    __shared__ __align__(16) float Ws[32][96];
    int tx = tid & 15, ty = tid >> 4;
    #pragma unroll 1
    for (int k0 = 0; k0 < DD; k0 += 32) {
        #pragma unroll
        for (int l = 0; l < 2; l++) {
            int e = tid + l*256;
            int r = e >> 3, k4 = e & 7;
            size_t off = (size_t)(m0 + r)*DD + k0 + k4*4;
            float4 u = *(const float4*)(T0 + off);
            float4 v = *(const float4*)(T1 + off);
            float4 w;
            w.x = lrelu(u.x + v.x); w.y = lrelu(u.y + v.y);
            w.z = lrelu(u.z + v.z); w.w = lrelu(u.w + v.w);
            *(float4*)&Xs[r][k4*4] = w;
        }
        #pragma unroll
        for (int l = 0; l < 3; l++) {
            int e = tid + l*256;
            int kk = e / 24, d4 = e % 24;
            *(float4*)&Ws[kk][d4*4] = *(const float4*)(W + (size_t)(k0 + kk)*DD + d4*4);
        }
        __syncthreads();
        step32_64(Xs, Ws, tx, ty, acc);
        __syncthreads();
    }
}

__global__ __launch_bounds__(256) void f1_kernel(
    const float* __restrict__ Wii, const float* __restrict__ bii)
{
    int br = blockIdx.y;
    int m0 = blockIdx.x * 64;
    int tid = threadIdx.x, tx = tid & 15, ty = tid >> 4;
    unsigned long long acc[4][3] = {};
    mm96(&g_h[br][0][0], Wii + (size_t)br*DD*DD, m0, tid, acc);
    #pragma unroll
    for (int i = 0; i < 4; i++) {
        int m = m0 + ty*4 + i;
        #pragma unroll
        for (int q = 0; q < 3; q++) {
            float2 v = unpack2(acc[i][q]);
            int c = tx*6 + 2*q;
            *(float2*)&g_t[br][m][c] = make_float2(v.x + bii[br*DD + c],
                                                   v.y + bii[br*DD + c + 1]);
        }
    }
}

__global__ __launch_bounds__(256) void f2_kernel(
    const float* __restrict__ Watt, const float* __restrict__ batt, float* __restrict__ out)
{
    int m0 = blockIdx.x * 64;
    int tid = threadIdx.x, tx = tid & 15, ty = tid >> 4;
    unsigned long long acc[4][3] = {};
    #pragma unroll 1
    for (int j = 0; j < 3; j++) {
        const float* T0 = &g_t[j][0][0];
        const float* T1 = &g_t[(j + 1) % 3][0][0];
        mm96pairL(T0, T1, Watt + (size_t)j*DD*DD, m0, tid, acc);
    }
    #pragma unroll
    for (int i = 0; i < 4; i++) {
        int m = m0 + ty*4 + i;
        #pragma unroll
        for (int q = 0; q < 3; q++) {
            float2 v = unpack2(acc[i][q]);
            int c = tx*6 + 2*q;
            float b0 = batt[c]     + batt[DD + c]     + batt[2*DD + c];
            float b1 = batt[c + 1] + batt[DD + c + 1] + batt[2*DD + c + 1];
            *(float2*)&out[(size_t)m*DD + c] = make_float2(v.x + b0, v.y + b1);
        }
    }
}

// =========================================================================
//  launch
// =========================================================================
extern "C" void kernel_launch(void* const* d_in, const int* in_sizes, int n_in,
                              void* d_out, int out_size)
{
    const float* x     = (const float*)d_in[0];
    const float* adjA  = (const float*)d_in[1];
    const float* adjB  = (const float*)d_in[2];
    const float* adjC  = (const float*)d_in[3];
    const float* mask  = (const float*)d_in[4];
    const float* mask1 = (const float*)d_in[5];
    const float* mask2 = (const float*)d_in[6];
    const float* Wenc  = (const float*)d_in[7];
    const float* benc  = (const float*)d_in[8];
    const float* Wii   = (const float*)d_in[9];
    const float* bii   = (const float*)d_in[10];
    const float* Wgru  = (const float*)d_in[11];
    const float* bgru  = (const float*)d_in[12];
    const float* Watt  = (const float*)d_in[13];
    const float* batt  = (const float*)d_in[14];
    float* out = (float*)d_out;

    cudaFuncSetAttribute(gates_kernel, cudaFuncAttributeMaxDynamicSharedMemorySize, GATES_SMEM);

    encode_kernel<<<dim3(MTOT/64, 3), 256>>>(x, Wenc, benc, mask, mask1, mask2);
    for (int s = 0; s < 2; s++) {
        msg_kernel  <<<dim3(NN/128, BB, 9), 256>>>(adjA, adjB, adjC);
        gates_kernel<<<dim3(MTOT/64, 3), 256, GATES_SMEM>>>(Wgru, bgru, mask, mask1, mask2);
    }
    f1_kernel<<<dim3(MTOT/64, 3), 256>>>(Wii, bii);
    f2_kernel<<<MTOT/64, 256>>>(Watt, batt, out);
}

// round 12
// speedup vs baseline: 1.0309x; 1.0309x over previous
#include <cuda_runtime.h>
#include <math.h>

#define BB   8
#define NN   2048
#define KDIN 300
#define DD   96
#define MTOT (BB*NN)   // 16384

// ---------------- scratch (no runtime allocation allowed) ----------------
__device__ __align__(128) float g_h[3][MTOT][DD];
__device__ __align__(128) float g_a[3][MTOT][DD];
__device__ __align__(128) float g_t[3][MTOT][DD];

// ---------------- helpers ----------------
__device__ __forceinline__ unsigned long long pack2(float x, float y) {
    unsigned long long r;
    asm("mov.b64 %0, {%1,%2};" : "=l"(r) : "f"(x), "f"(y));
    return r;
}
__device__ __forceinline__ float2 unpack2(unsigned long long v) {
    float2 f;
    asm("mov.b64 {%0,%1}, %2;" : "=f"(f.x), "=f"(f.y) : "l"(v));
    return f;
}
__device__ __forceinline__ void ffma2(unsigned long long& acc, unsigned long long a, unsigned long long b) {
    asm("fma.rn.f32x2 %0, %1, %2, %0;" : "+l"(acc) : "l"(a), "l"(b));
}
__device__ __forceinline__ void cpa16(void* s, const void* g) {
    unsigned su = (unsigned)__cvta_generic_to_shared(s);
    asm volatile("cp.async.cg.shared.global [%0], [%1], 16;" :: "r"(su), "l"(g));
}
__device__ __forceinline__ void cp_commit() { asm volatile("cp.async.commit_group;"); }
__device__ __forceinline__ void cp_wait1()  { asm volatile("cp.async.wait_group 1;"); }
__device__ __forceinline__ void cp_wait0()  { asm volatile("cp.async.wait_group 0;"); }
__device__ __forceinline__ float sigmoidf_(float x) { return 1.f / (1.f + expf(-x)); }
__device__ __forceinline__ float lrelu(float v)     { return v > 0.f ? v : 0.2f * v; }

// =========================================================================
//  ENCODE: h_i = mask_i * relu(x @ W_enc[i] + b_enc[i])
// =========================================================================
__device__ __forceinline__ void step32_64(const float Xs[64][32], const float Ws[32][96],
                                          int tx, int ty, unsigned long long acc[4][3])
{
    #pragma unroll
    for (int k = 0; k < 32; k++) {
        unsigned long long bp[3];
        #pragma unroll
        for (int q = 0; q < 3; q++)
            bp[q] = *(const unsigned long long*)&Ws[k][tx*6 + 2*q];
        #pragma unroll
        for (int i = 0; i < 4; i++) {
            float a = Xs[ty*4 + i][k];
            unsigned long long ap = pack2(a, a);
            #pragma unroll
            for (int q = 0; q < 3; q++) ffma2(acc[i][q], ap, bp[q]);
        }
    }
}

__global__ __launch_bounds__(256) void encode_kernel(
    const float* __restrict__ x, const float* __restrict__ Wenc, const float* __restrict__ benc,
    const float* __restrict__ mk0, const float* __restrict__ mk1, const float* __restrict__ mk2)
{
    __shared__ __align__(16) float Xs[64][32];
    __shared__ __align__(16) float Ws[32][96];
    int br = blockIdx.y;
    int m0 = blockIdx.x * 64;
    const float* mask = (br == 0) ? mk0 : ((br == 1) ? mk1 : mk2);
    const float* W = Wenc + (size_t)br * KDIN * DD;
    int tid = threadIdx.x, tx = tid & 15, ty = tid >> 4;
    unsigned long long acc[4][3] = {};
    #pragma unroll 1
    for (int k0 = 0; k0 < 320; k0 += 32) {
        #pragma unroll
        for (int l = 0; l < 8; l++) {
            int e = tid + l*256;
            int r = e >> 5, k = e & 31;
            int kk = k0 + k;
            Xs[r][k] = (kk < KDIN) ? x[(size_t)(m0 + r)*KDIN + kk] : 0.f;
        }
        #pragma unroll
        for (int l = 0; l < 12; l++) {
            int e = tid + l*256;
            int kk = e / 96, d = e % 96;
            int kg = k0 + kk;
            Ws[kk][d] = (kg < KDIN) ? W[(size_t)kg*DD + d] : 0.f;
        }
        __syncthreads();
        step32_64(Xs, Ws, tx, ty, acc);
        __syncthreads();
    }
    #pragma unroll
    for (int i = 0; i < 4; i++) {
        int m = m0 + ty*4 + i;
        float mkv = mask[m];
        #pragma unroll
        for (int q = 0; q < 3; q++) {
            float2 v = unpack2(acc[i][q]);
            int c = tx*6 + 2*q;
            float o0 = fmaxf(v.x + benc[br*DD + c],     0.f) * mkv;
            float o1 = fmaxf(v.y + benc[br*DD + c + 1], 0.f) * mkv;
            *(float2*)&g_h[br][m][c] = make_float2(o0, o1);
        }
    }
}

// =========================================================================
//  MESSAGE PASSING v4b: a = adj @ h
//  R8 inner loop (smem A, float2 k-pairs) + cp.async double buffering of
//  BOTH tiles. 128 thr, 64-row x 96-col tile, full K=2048 (no split).
//  grid = 32 x 8 x 3 = 768 blocks ~ 1.04 waves at occ 5.
//  FIX vs R11: Hs loader covers all 768 float4 (6 x 128), not 192.
// =========================================================================
__global__ __launch_bounds__(128, 5) void msg_kernel(
    const float* __restrict__ adjA, const float* __restrict__ adjB, const float* __restrict__ adjC)
{
    __shared__ __align__(16) float As[2][64][32];
    __shared__ __align__(16) float Hs[2][32][96];
    int br = blockIdx.z;
    int b  = blockIdx.y;
    int n0 = blockIdx.x * 64;
    const float* adj = ((br == 0) ? adjA : ((br == 1) ? adjB : adjC)) + (size_t)b * NN * NN;
    const float* H   = &g_h[br][b * NN][0];
    float* Ao = &g_a[br][b * NN][0];
    int tid = threadIdx.x, tx = tid & 15, ty = tid >> 4;   // ty 0..7, 8 rows each

    unsigned long long acc[8][3] = {};

    // prologue: chunk 0 -> buf 0
    {
        const float* aSrc = adj + (size_t)n0 * NN;
        #pragma unroll
        for (int l = 0; l < 4; l++) {
            int e = tid + l*128; int r = e >> 3, k4 = e & 7;
            cpa16(&As[0][r][k4*4], aSrc + (size_t)r*NN + k4*4);
        }
        #pragma unroll
        for (int l = 0; l < 6; l++) {                      // 768 float4 total
            int e = tid + l*128; int kk = e / 24, d4 = e % 24;
            cpa16(&Hs[0][kk][d4*4], H + (size_t)kk*DD + d4*4);
        }
        cp_commit();
    }

    #pragma unroll 1
    for (int c = 0; c < 64; c++) {
        if (c < 63) {
            int nb = (c + 1) & 1;
            const float* aSrc = adj + (size_t)n0 * NN + (c + 1)*32;
            #pragma unroll
            for (int l = 0; l < 4; l++) {
                int e = tid + l*128; int r = e >> 3, k4 = e & 7;
                cpa16(&As[nb][r][k4*4], aSrc + (size_t)r*NN + k4*4);
            }
            const float* Hc = H + (size_t)(c + 1)*32*DD;
            #pragma unroll
            for (int l = 0; l < 6; l++) {
                int e = tid + l*128; int kk = e / 24, d4 = e % 24;
                cpa16(&Hs[nb][kk][d4*4], Hc + (size_t)kk*DD + d4*4);
            }
            cp_commit();
            cp_wait1();
        } else {
            cp_wait0();
        }
        __syncthreads();

        const float (*Ab)[32] = As[c & 1];
        const float (*Hb)[96] = Hs[c & 1];
        #pragma unroll
        for (int k2 = 0; k2 < 16; k2++) {
            float2 av[8];
            #pragma unroll
            for (int i = 0; i < 8; i++)
                av[i] = *(const float2*)&Ab[ty*8 + i][k2*2];
            #pragma unroll
            for (int kk = 0; kk < 2; kk++) {
                unsigned long long bp0 = *(const unsigned long long*)&Hb[k2*2 + kk][tx*6 + 0];
                unsigned long long bp1 = *(const unsigned long long*)&Hb[k2*2 + kk][tx*6 + 2];
                unsigned long long bp2 = *(const unsigned long long*)&Hb[k2*2 + kk][tx*6 + 4];
                #pragma unroll
                for (int i = 0; i < 8; i++) {
                    float a = kk ? av[i].y : av[i].x;
                    unsigned long long ap = pack2(a, a);
                    ffma2(acc[i][0], ap, bp0);
                    ffma2(acc[i][1], ap, bp1);
                    ffma2(acc[i][2], ap, bp2);
                }
            }
        }
        __syncthreads();
    }

    #pragma unroll
    for (int i = 0; i < 8; i++) {
        int n = n0 + ty*8 + i;
        #pragma unroll
        for (int q = 0; q < 3; q++) {
            float2 v = unpack2(acc[i][q]);
            *(float2*)&Ao[(size_t)n*DD + tx*6 + 2*q] = v;
        }
    }
}

// =========================================================================
//  FUSED GRU GATES v2: flat 18-chunk cp.async weight pipeline.
//  gemm order: z0(a) z1(h) | h0(a) | r0(a) r1(h) | [rh -> a_s] h1(rh)
//  chunks g = c/3 in {0..5}, weight idx {0,1,4,2,3,5}, X in {a,h,a,a,h,a_s}
// =========================================================================
#define GATES_SMEM ((64*96 + 64*96 + 2*32*96) * 4)

__global__ __launch_bounds__(256, 2) void gates_kernel(
    const float* __restrict__ Wgru, const float* __restrict__ bgru,
    const float* __restrict__ mk0, const float* __restrict__ mk1, const float* __restrict__ mk2)
{
    extern __shared__ float dsm[];
    float (*a_s)[96] = (float(*)[96])dsm;                  // reused for r*h at the end
    float (*h_s)[96] = (float(*)[96])(dsm + 64*96);
    float (*w_s)[32][96] = (float(*)[32][96])(dsm + 2*64*96);

    int br = blockIdx.y;
    int m0 = blockIdx.x * 64;
    const float* mask = (br == 0) ? mk0 : ((br == 1) ? mk1 : mk2);
    const float* Wb = Wgru + (size_t)(br*6) * DD * DD;     // z0,z1,r0,r1,h0,h1
    const float* bb = bgru + (size_t)(br*6) * DD;
    int tid = threadIdx.x, tx = tid & 15, ty = tid >> 4;

    const int wsel[6] = {0, 1, 4, 2, 3, 5};                // weight matrix per gemm

    // issue chunk 0
    {
        const float* Wc = Wb + (size_t)wsel[0]*DD*DD;
        #pragma unroll
        for (int l = 0; l < 3; l++) {
            int e = tid + l*256; int kk = e / 24, d4 = e % 24;
            cpa16(&w_s[0][kk][d4*4], Wc + (size_t)kk*DD + d4*4);
        }
        cp_commit();
    }

    // load a_s and h_s (plain; published by chunk-0 barrier)
    #pragma unroll
    for (int l = 0; l < 6; l++) {
        int e = tid + l*256;
        int r = e / 24, d4 = e % 24;
        *(float4*)&a_s[r][d4*4] = *(const float4*)&g_a[br][m0 + r][d4*4];
        *(float4*)&h_s[r][d4*4] = *(const float4*)&g_h[br][m0 + r][d4*4];
    }

    unsigned long long acc[4][3] = {};
    float2 zr[4][3], hp[4][3];

    #pragma unroll 1
    for (int c = 0; c < 18; c++) {
        if (c < 17) {
            int g1 = (c + 1) / 3, k1 = (c + 1) % 3;
            const float* Wc = Wb + (size_t)wsel[g1]*DD*DD + (size_t)k1*32*DD;
            int nb = (c + 1) & 1;
            #pragma unroll
            for (int l = 0; l < 3; l++) {
                int e = tid + l*256; int kk = e / 24, d4 = e % 24;
                cpa16(&w_s[nb][kk][d4*4], Wc + (size_t)kk*DD + d4*4);
            }
            cp_commit();
            cp_wait1();
        } else {
            cp_wait0();
        }
        __syncthreads();

        int g = c / 3, kc = c % 3;
        const float (*X)[96] = (g == 1 || g == 4) ? h_s : a_s;
        const float (*Wt)[96] = w_s[c & 1];
        #pragma unroll
        for (int k2 = 0; k2 < 16; k2++) {
            float2 av[4];
            #pragma unroll
            for (int i = 0; i < 4; i++)
                av[i] = *(const float2*)&X[ty*4 + i][kc*32 + k2*2];
            #pragma unroll
            for (int kk = 0; kk < 2; kk++) {
                unsigned long long bp[3];
                #pragma unroll
                for (int q = 0; q < 3; q++)
                    bp[q] = *(const unsigned long long*)&Wt[k2*2 + kk][tx*6 + 2*q];
                #pragma unroll
                for (int i = 0; i < 4; i++) {
                    float a = kk ? av[i].y : av[i].x;
                    unsigned long long ap = pack2(a, a);
                    #pragma unroll
                    for (int q = 0; q < 3; q++) ffma2(acc[i][q], ap, bp[q]);
                }
            }
        }
        __syncthreads();

        if (c == 5) {                                      // z ready
            #pragma unroll
            for (int i = 0; i < 4; i++)
                #pragma unroll
                for (int q = 0; q < 3; q++) {
                    float2 v = unpack2(acc[i][q]);
                    int cc = tx*6 + 2*q;
                    zr[i][q].x = sigmoidf_(v.x + bb[0*DD + cc]     + bb[1*DD + cc]);
                    zr[i][q].y = sigmoidf_(v.y + bb[0*DD + cc + 1] + bb[1*DD + cc + 1]);
                    acc[i][q] = 0ull;
                }
        } else if (c == 8) {                               // hp = a@Wh0 ready
            #pragma unroll
            for (int i = 0; i < 4; i++)
                #pragma unroll
                for (int q = 0; q < 3; q++) {
                    hp[i][q] = unpack2(acc[i][q]);
                    acc[i][q] = 0ull;
                }
        } else if (c == 14) {                              // r ready; rh -> a_s
            #pragma unroll
            for (int i = 0; i < 4; i++)
                #pragma unroll
                for (int q = 0; q < 3; q++) {
                    float2 v = unpack2(acc[i][q]);
                    int cc = tx*6 + 2*q;
                    float2 hv = *(const float2*)&h_s[ty*4 + i][cc];
                    float r0 = sigmoidf_(v.x + bb[2*DD + cc]     + bb[3*DD + cc]);
                    float r1 = sigmoidf_(v.y + bb[2*DD + cc + 1] + bb[3*DD + cc + 1]);
                    *(float2*)&a_s[ty*4 + i][cc] = make_float2(r0*hv.x, r1*hv.y);
                    acc[i][q] = 0ull;
                }
            // a_s writes published by chunk-15's pre-compute __syncthreads
        }
    }

    // blend: hh = relu(mask*(hp + bh0 + rh@Wh1 + bh1)); h = hh*z + h*(1-z)
    #pragma unroll
    for (int i = 0; i < 4; i++) {
        int m = m0 + ty*4 + i;
        float mkv = mask[m];
        #pragma unroll
        for (int q = 0; q < 3; q++) {
            float2 v = unpack2(acc[i][q]);
            int cc = tx*6 + 2*q;
            float2 hv = *(const float2*)&h_s[ty*4 + i][cc];
            float hh0 = fmaxf(mkv * (v.x + hp[i][q].x + bb[4*DD + cc]     + bb[5*DD + cc]),     0.f);
            float hh1 = fmaxf(mkv * (v.y + hp[i][q].y + bb[4*DD + cc + 1] + bb[5*DD + cc + 1]), 0.f);
            float o0 = hh0*zr[i][q].x + hv.x*(1.f - zr[i][q].x);
            float o1 = hh1*zr[i][q].y + hv.y*(1.f - zr[i][q].y);
            *(float2*)&g_h[br][m][cc] = make_float2(o0, o1);
        }
    }
}

// =========================================================================
//  f1 / f2
// =========================================================================
__device__ __forceinline__ void mm96(const float* __restrict__ In, const float* __restrict__ W,
                                     int m0, int tid, unsigned long long acc[4][3])
{
    __shared__ __align__(16) float Xs[64][32];
    __shared__ __align__(16) float Ws[32][96];
    int tx = tid & 15, ty = tid >> 4;
    #pragma unroll 1
    for (int k0 = 0; k0 < DD; k0 += 32) {
        #pragma unroll
        for (int l = 0; l < 2; l++) {
            int e = tid + l*256;
            int r = e >> 3, k4 = e & 7;
            *(float4*)&Xs[r][k4*4] = *(const float4*)(In + (size_t)(m0 + r)*DD + k0 + k4*4);
        }
        #pragma unroll
        for (int l = 0; l < 3; l++) {
            int e = tid + l*256;
            int kk = e / 24, d4 = e % 24;
            *(float4*)&Ws[kk][d4*4] = *(const float4*)(W + (size_t)(k0 + kk)*DD + d4*4);
        }
        __syncthreads();
        step32_64(Xs, Ws, tx, ty, acc);
        __syncthreads();
    }
}

__device__ __forceinline__ void mm96pairL(const float* __restrict__ T0, const float* __restrict__ T1,
                                          const float* __restrict__ W, int m0, int tid,
                                          unsigned long long acc[4][3])
{
    __shared__ __align__(16) float Xs[64][32];
    __shared__ __align__(16) float Ws[32][96];
    int tx = tid & 15, ty = tid >> 4;
    #pragma unroll 1
    for (int k0 = 0; k0 < DD; k0 += 32) {
        #pragma unroll
        for (int l = 0; l < 2; l++) {
            int e = tid + l*256;
            int r = e >> 3, k4 = e & 7;
            size_t off = (size_t)(m0 + r)*DD + k0 + k4*4;
            float4 u = *(const float4*)(T0 + off);
            float4 v = *(const float4*)(T1 + off);
            float4 w;
            w.x = lrelu(u.x + v.x); w.y = lrelu(u.y + v.y);
            w.z = lrelu(u.z + v.z); w.w = lrelu(u.w + v.w);
            *(float4*)&Xs[r][k4*4] = w;
        }
        #pragma unroll
        for (int l = 0; l < 3; l++) {
            int e = tid + l*256;
            int kk = e / 24, d4 = e % 24;
            *(float4*)&Ws[kk][d4*4] = *(const float4*)(W + (size_t)(k0 + kk)*DD + d4*4);
        }
        __syncthreads();
        step32_64(Xs, Ws, tx, ty, acc);
        __syncthreads();
    }
}

__global__ __launch_bounds__(256) void f1_kernel(
    const float* __restrict__ Wii, const float* __restrict__ bii)
{
    int br = blockIdx.y;
    int m0 = blockIdx.x * 64;
    int tid = threadIdx.x, tx = tid & 15, ty = tid >> 4;
    unsigned long long acc[4][3] = {};
    mm96(&g_h[br][0][0], Wii + (size_t)br*DD*DD, m0, tid, acc);
    #pragma unroll
    for (int i = 0; i < 4; i++) {
        int m = m0 + ty*4 + i;
        #pragma unroll
        for (int q = 0; q < 3; q++) {
            float2 v = unpack2(acc[i][q]);
            int c = tx*6 + 2*q;
            *(float2*)&g_t[br][m][c] = make_float2(v.x + bii[br*DD + c],
                                                   v.y + bii[br*DD + c + 1]);
        }
    }
}

__global__ __launch_bounds__(256) void f2_kernel(
    const float* __restrict__ Watt, const float* __restrict__ batt, float* __restrict__ out)
{
    int m0 = blockIdx.x * 64;
    int tid = threadIdx.x, tx = tid & 15, ty = tid >> 4;
    unsigned long long acc[4][3] = {};
    #pragma unroll 1
    for (int j = 0; j < 3; j++) {
        const float* T0 = &g_t[j][0][0];
        const float* T1 = &g_t[(j + 1) % 3][0][0];
        mm96pairL(T0, T1, Watt + (size_t)j*DD*DD, m0, tid, acc);
    }
    #pragma unroll
    for (int i = 0; i < 4; i++) {
        int m = m0 + ty*4 + i;
        #pragma unroll
        for (int q = 0; q < 3; q++) {
            float2 v = unpack2(acc[i][q]);
            int c = tx*6 + 2*q;
            float b0 = batt[c]     + batt[DD + c]     + batt[2*DD + c];
            float b1 = batt[c + 1] + batt[DD + c + 1] + batt[2*DD + c + 1];
            *(float2*)&out[(size_t)m*DD + c] = make_float2(v.x + b0, v.y + b1);
        }
    }
}

// =========================================================================
//  launch
// =========================================================================
extern "C" void kernel_launch(void* const* d_in, const int* in_sizes, int n_in,
                              void* d_out, int out_size)
{
    const float* x     = (const float*)d_in[0];
    const float* adjA  = (const float*)d_in[1];
    const float* adjB  = (const float*)d_in[2];
    const float* adjC  = (const float*)d_in[3];
    const float* mask  = (const float*)d_in[4];
    const float* mask1 = (const float*)d_in[5];
    const float* mask2 = (const float*)d_in[6];
    const float* Wenc  = (const float*)d_in[7];
    const float* benc  = (const float*)d_in[8];
    const float* Wii   = (const float*)d_in[9];
    const float* bii   = (const float*)d_in[10];
    const float* Wgru  = (const float*)d_in[11];
    const float* bgru  = (const float*)d_in[12];
    const float* Watt  = (const float*)d_in[13];
    const float* batt  = (const float*)d_in[14];
    float* out = (float*)d_out;

    cudaFuncSetAttribute(gates_kernel, cudaFuncAttributeMaxDynamicSharedMemorySize, GATES_SMEM);

    encode_kernel<<<dim3(MTOT/64, 3), 256>>>(x, Wenc, benc, mask, mask1, mask2);
    for (int s = 0; s < 2; s++) {
        msg_kernel  <<<dim3(NN/64, BB, 3), 128>>>(adjA, adjB, adjC);
        gates_kernel<<<dim3(MTOT/64, 3), 256, GATES_SMEM>>>(Wgru, bgru, mask, mask1, mask2);
    }
    f1_kernel<<<dim3(MTOT/64, 3), 256>>>(Wii, bii);
    f2_kernel<<<MTOT/64, 256>>>(Watt, batt, out);
}

// round 16
// speedup vs baseline: 1.1134x; 1.0800x over previous
#include <cuda_runtime.h>
#include <cuda_bf16.h>
#include <cstdint>
#include <math.h>

#define BB   8
#define NN   2048
#define KDIN 300
#define DD   96
#define MTOT (BB*NN)   // 16384

// ---------------- scratch (no runtime allocation allowed) ----------------
__device__ __align__(128) float g_h[3][MTOT][DD];
__device__ __align__(128) float g_a[3][MTOT][DD];
__device__ __align__(128) float g_t[3][MTOT][DD];
// split-bf16 operands for tensor-core msg GEMM
__device__ __align__(128) __nv_bfloat16 g_adj_hi[3][BB][NN][NN];
__device__ __align__(128) __nv_bfloat16 g_adj_lo[3][BB][NN][NN];
__device__ __align__(128) __nv_bfloat16 g_hT_hi[3][BB][DD][NN];
__device__ __align__(128) __nv_bfloat16 g_hT_lo[3][BB][DD][NN];

// ---------------- scalar helpers ----------------
__device__ __forceinline__ unsigned long long pack2(float x, float y) {
    unsigned long long r;
    asm("mov.b64 %0, {%1,%2};" : "=l"(r) : "f"(x), "f"(y));
    return r;
}
__device__ __forceinline__ float2 unpack2(unsigned long long v) {
    float2 f;
    asm("mov.b64 {%0,%1}, %2;" : "=f"(f.x), "=f"(f.y) : "l"(v));
    return f;
}
__device__ __forceinline__ void ffma2(unsigned long long& acc, unsigned long long a, unsigned long long b) {
    asm("fma.rn.f32x2 %0, %1, %2, %0;" : "+l"(acc) : "l"(a), "l"(b));
}
__device__ __forceinline__ void cpa16(void* s, const void* g) {
    unsigned su = (unsigned)__cvta_generic_to_shared(s);
    asm volatile("cp.async.cg.shared.global [%0], [%1], 16;" :: "r"(su), "l"(g));
}
__device__ __forceinline__ void cp_commit() { asm volatile("cp.async.commit_group;"); }
__device__ __forceinline__ void cp_wait1()  { asm volatile("cp.async.wait_group 1;"); }
__device__ __forceinline__ void cp_wait0()  { asm volatile("cp.async.wait_group 0;"); }
__device__ __forceinline__ float sigmoidf_(float x) { return 1.f / (1.f + expf(-x)); }
__device__ __forceinline__ float lrelu(float v)     { return v > 0.f ? v : 0.2f * v; }

// warp-level bf16 MMA (baseline PTX, works on plain sm_103 target)
__device__ __forceinline__ void mma16816(float* d, const uint32_t* a, uint32_t b0, uint32_t b1) {
    asm volatile(
        "mma.sync.aligned.m16n8k16.row.col.f32.bf16.bf16.f32 "
        "{%0,%1,%2,%3}, {%4,%5,%6,%7}, {%8,%9}, {%0,%1,%2,%3};"
        : "+f"(d[0]), "+f"(d[1]), "+f"(d[2]), "+f"(d[3])
        : "r"(a[0]), "r"(a[1]), "r"(a[2]), "r"(a[3]), "r"(b0), "r"(b1));
}

// =========================================================================
//  CONVERSIONS
// =========================================================================
__global__ __launch_bounds__(256) void conv_adj_kernel(
    const float* __restrict__ A0, const float* __restrict__ A1, const float* __restrict__ A2)
{
    int br = blockIdx.z, b = blockIdx.y;
    const float* src = ((br == 0) ? A0 : ((br == 1) ? A1 : A2)) + (size_t)b * NN * NN;
    size_t idx = (size_t)blockIdx.x * 256 + threadIdx.x;     // float4 index
    float4 v = ((const float4*)src)[idx];
    __nv_bfloat16 h0 = __float2bfloat16(v.x), l0 = __float2bfloat16(v.x - __bfloat162float(h0));
    __nv_bfloat16 h1 = __float2bfloat16(v.y), l1 = __float2bfloat16(v.y - __bfloat162float(h1));
    __nv_bfloat16 h2 = __float2bfloat16(v.z), l2 = __float2bfloat16(v.z - __bfloat162float(h2));
    __nv_bfloat16 h3 = __float2bfloat16(v.w), l3 = __float2bfloat16(v.w - __bfloat162float(h3));
    uint2 ph, pl;
    ph.x = ((uint32_t)__bfloat16_as_ushort(h1) << 16) | __bfloat16_as_ushort(h0);
    ph.y = ((uint32_t)__bfloat16_as_ushort(h3) << 16) | __bfloat16_as_ushort(h2);
    pl.x = ((uint32_t)__bfloat16_as_ushort(l1) << 16) | __bfloat16_as_ushort(l0);
    pl.y = ((uint32_t)__bfloat16_as_ushort(l3) << 16) | __bfloat16_as_ushort(l2);
    ((uint2*)&g_adj_hi[br][b][0][0])[idx] = ph;
    ((uint2*)&g_adj_lo[br][b][0][0])[idx] = pl;
}

// h [64 rows x 96] -> transposed bf16 hi/lo [96][2048]
__global__ __launch_bounds__(256) void conv_hT_kernel()
{
    __shared__ float hs[64][97];
    int br = blockIdx.y;
    int m0 = blockIdx.x * 64;
    int b  = m0 / NN, bm = m0 % NN;
    int tid = threadIdx.x;
    #pragma unroll
    for (int l = 0; l < 6; l++) {
        int e = tid + l*256;                     // float4 idx 0..1535
        int r = e / 24, d4 = e % 24;
        float4 v = *(const float4*)&g_h[br][m0 + r][d4*4];
        hs[r][d4*4 + 0] = v.x; hs[r][d4*4 + 1] = v.y;
        hs[r][d4*4 + 2] = v.z; hs[r][d4*4 + 3] = v.w;
    }
    __syncthreads();
    int w = tid >> 5, lane = tid & 31;
    #pragma unroll 1
    for (int d0 = 0; d0 < DD; d0 += 8) {
        int d = d0 + w;
        #pragma unroll
        for (int half = 0; half < 2; half++) {
            int ml = half*32 + lane;
            float x = hs[ml][d];
            __nv_bfloat16 h = __float2bfloat16(x);
            __nv_bfloat16 lo = __float2bfloat16(x - __bfloat162float(h));
            g_hT_hi[br][b][d][bm + ml] = h;
            g_hT_lo[br][b][d][bm + ml] = lo;
        }
    }
}

// =========================================================================
//  MESSAGE PASSING via warp MMA: a = adj @ h, split-bf16 3-pass
//  CTA: 128 rows x 96 cols, 128 thr = 4 warps x m32. K chunks of 64.
//  A frags straight from global; B (hT) tile in smem (pad stride 72 bf16).
// =========================================================================
#define KC   64
#define BPAD 72

__global__ __launch_bounds__(128) void msg_mma_kernel()
{
    __shared__ __nv_bfloat16 bs_hi[DD * BPAD];
    __shared__ __nv_bfloat16 bs_lo[DD * BPAD];
    int tid = threadIdx.x, w = tid >> 5, lane = tid & 31;
    int g = lane >> 2, tg = lane & 3;
    int br = blockIdx.z, b = blockIdx.y, n0 = blockIdx.x * 128;
    const __nv_bfloat16* aHi = &g_adj_hi[br][b][0][0];
    const __nv_bfloat16* aLo = &g_adj_lo[br][b][0][0];
    const __nv_bfloat16* bHi = &g_hT_hi[br][b][0][0];
    const __nv_bfloat16* bLo = &g_hT_lo[br][b][0][0];

    float acc[2][12][4];
    #pragma unroll
    for (int mt = 0; mt < 2; mt++)
        #pragma unroll
        for (int nt = 0; nt < 12; nt++)
            #pragma unroll
            for (int q = 0; q < 4; q++) acc[mt][nt][q] = 0.f;

    int rowg = n0 + w*32 + g;                    // A row for group, mt adds 16

    #pragma unroll 1
    for (int c = 0; c < NN/KC; c++) {
        int k0 = c * KC;
        // stage B tile (96 x 64 bf16, hi+lo) via cp.async
        #pragma unroll
        for (int l = 0; l < 6; l++) {
            int e = tid + l*128;                 // 0..767
            int n = e >> 3, k4 = e & 7;
            cpa16(&bs_hi[n*BPAD + k4*8], bHi + (size_t)n*NN + k0 + k4*8);
            cpa16(&bs_lo[n*BPAD + k4*8], bLo + (size_t)n*NN + k0 + k4*8);
        }
        cp_commit();
        cp_wait0();
        __syncthreads();

        #pragma unroll
        for (int ks = 0; ks < KC/16; ks++) {
            int kk = k0 + ks*16;
            // A fragments (hi & lo) for both m-tiles, direct from global
            uint32_t Ah[2][4], Al[2][4];
            #pragma unroll
            for (int mt = 0; mt < 2; mt++) {
                size_t r0 = (size_t)(rowg + mt*16) * NN;
                size_t r8 = (size_t)(rowg + mt*16 + 8) * NN;
                Ah[mt][0] = *(const uint32_t*)(aHi + r0 + kk + tg*2);
                Ah[mt][1] = *(const uint32_t*)(aHi + r8 + kk + tg*2);
                Ah[mt][2] = *(const uint32_t*)(aHi + r0 + kk + tg*2 + 8);
                Ah[mt][3] = *(const uint32_t*)(aHi + r8 + kk + tg*2 + 8);
                Al[mt][0] = *(const uint32_t*)(aLo + r0 + kk + tg*2);
                Al[mt][1] = *(const uint32_t*)(aLo + r8 + kk + tg*2);
                Al[mt][2] = *(const uint32_t*)(aLo + r0 + kk + tg*2 + 8);
                Al[mt][3] = *(const uint32_t*)(aLo + r8 + kk + tg*2 + 8);
            }
            int ksl = ks*16;
            #pragma unroll
            for (int nt = 0; nt < 12; nt++) {
                int boff = (nt*8 + g)*BPAD + ksl + tg*2;
                uint32_t bh0 = *(const uint32_t*)&bs_hi[boff];
                uint32_t bh1 = *(const uint32_t*)&bs_hi[boff + 8];
                uint32_t bl0 = *(const uint32_t*)&bs_lo[boff];
                uint32_t bl1 = *(const uint32_t*)&bs_lo[boff + 8];
                #pragma unroll
                for (int mt = 0; mt < 2; mt++) {
                    mma16816(acc[mt][nt], Ah[mt], bh0, bh1);
                    mma16816(acc[mt][nt], Ah[mt], bl0, bl1);
                    mma16816(acc[mt][nt], Al[mt], bh0, bh1);
                }
            }
        }
        __syncthreads();
    }

    // write out: c0,c1 -> (row g, col tg*2..+1); c2,c3 -> (row g+8)
    #pragma unroll
    for (int mt = 0; mt < 2; mt++) {
        int row = rowg + mt*16;
        #pragma unroll
        for (int nt = 0; nt < 12; nt++) {
            int col = nt*8 + tg*2;
            *(float2*)&g_a[br][b*NN + row][col]     = make_float2(acc[mt][nt][0], acc[mt][nt][1]);
            *(float2*)&g_a[br][b*NN + row + 8][col] = make_float2(acc[mt][nt][2], acc[mt][nt][3]);
        }
    }
}

// =========================================================================
//  ENCODE (unchanged)
// =========================================================================
__device__ __forceinline__ void step32_64(const float Xs[64][32], const float Ws[32][96],
                                          int tx, int ty, unsigned long long acc[4][3])
{
    #pragma unroll
    for (int k = 0; k < 32; k++) {
        unsigned long long bp[3];
        #pragma unroll
        for (int q = 0; q < 3; q++)
            bp[q] = *(const unsigned long long*)&Ws[k][tx*6 + 2*q];
        #pragma unroll
        for (int i = 0; i < 4; i++) {
            float a = Xs[ty*4 + i][k];
            unsigned long long ap = pack2(a, a);
            #pragma unroll
            for (int q = 0; q < 3; q++) ffma2(acc[i][q], ap, bp[q]);
        }
    }
}

__global__ __launch_bounds__(256) void encode_kernel(
    const float* __restrict__ x, const float* __restrict__ Wenc, const float* __restrict__ benc,
    const float* __restrict__ mk0, const float* __restrict__ mk1, const float* __restrict__ mk2)
{
    __shared__ __align__(16) float Xs[64][32];
    __shared__ __align__(16) float Ws[32][96];
    int br = blockIdx.y;
    int m0 = blockIdx.x * 64;
    const float* mask = (br == 0) ? mk0 : ((br == 1) ? mk1 : mk2);
    const float* W = Wenc + (size_t)br * KDIN * DD;
    int tid = threadIdx.x, tx = tid & 15, ty = tid >> 4;
    unsigned long long acc[4][3] = {};
    #pragma unroll 1
    for (int k0 = 0; k0 < 320; k0 += 32) {
        #pragma unroll
        for (int l = 0; l < 8; l++) {
            int e = tid + l*256;
            int r = e >> 5, k = e & 31;
            int kk = k0 + k;
            Xs[r][k] = (kk < KDIN) ? x[(size_t)(m0 + r)*KDIN + kk] : 0.f;
        }
        #pragma unroll
        for (int l = 0; l < 12; l++) {
            int e = tid + l*256;
            int kk = e / 96, d = e % 96;
            int kg = k0 + kk;
            Ws[kk][d] = (kg < KDIN) ? W[(size_t)kg*DD + d] : 0.f;
        }
        __syncthreads();
        step32_64(Xs, Ws, tx, ty, acc);
        __syncthreads();
    }
    #pragma unroll
    for (int i = 0; i < 4; i++) {
        int m = m0 + ty*4 + i;
        float mkv = mask[m];
        #pragma unroll
        for (int q = 0; q < 3; q++) {
            float2 v = unpack2(acc[i][q]);
            int c = tx*6 + 2*q;
            float o0 = fmaxf(v.x + benc[br*DD + c],     0.f) * mkv;
            float o1 = fmaxf(v.y + benc[br*DD + c + 1], 0.f) * mkv;
            *(float2*)&g_h[br][m][c] = make_float2(o0, o1);
        }
    }
}

// =========================================================================
//  FUSED GRU GATES (R12, unchanged)
// =========================================================================
#define GATES_SMEM ((64*96 + 64*96 + 2*32*96) * 4)

__global__ __launch_bounds__(256, 2) void gates_kernel(
    const float* __restrict__ Wgru, const float* __restrict__ bgru,
    const float* __restrict__ mk0, const float* __restrict__ mk1, const float* __restrict__ mk2)
{
    extern __shared__ float dsm[];
    float (*a_s)[96] = (float(*)[96])dsm;
    float (*h_s)[96] = (float(*)[96])(dsm + 64*96);
    float (*w_s)[32][96] = (float(*)[32][96])(dsm + 2*64*96);

    int br = blockIdx.y;
    int m0 = blockIdx.x * 64;
    const float* mask = (br == 0) ? mk0 : ((br == 1) ? mk1 : mk2);
    const float* Wb = Wgru + (size_t)(br*6) * DD * DD;
    const float* bb = bgru + (size_t)(br*6) * DD;
    int tid = threadIdx.x, tx = tid & 15, ty = tid >> 4;

    const int wsel[6] = {0, 1, 4, 2, 3, 5};

    {
        const float* Wc = Wb + (size_t)wsel[0]*DD*DD;
        #pragma unroll
        for (int l = 0; l < 3; l++) {
            int e = tid + l*256; int kk = e / 24, d4 = e % 24;
            cpa16(&w_s[0][kk][d4*4], Wc + (size_t)kk*DD + d4*4);
        }
        cp_commit();
    }

    #pragma unroll
    for (int l = 0; l < 6; l++) {
        int e = tid + l*256;
        int r = e / 24, d4 = e % 24;
        *(float4*)&a_s[r][d4*4] = *(const float4*)&g_a[br][m0 + r][d4*4];
        *(float4*)&h_s[r][d4*4] = *(const float4*)&g_h[br][m0 + r][d4*4];
    }

    unsigned long long acc[4][3] = {};
    float2 zr[4][3], hp[4][3];

    #pragma unroll 1
    for (int c = 0; c < 18; c++) {
        if (c < 17) {
            int g1 = (c + 1) / 3, k1 = (c + 1) % 3;
            const float* Wc = Wb + (size_t)wsel[g1]*DD*DD + (size_t)k1*32*DD;
            int nb = (c + 1) & 1;
            #pragma unroll
            for (int l = 0; l < 3; l++) {
                int e = tid + l*256; int kk = e / 24, d4 = e % 24;
                cpa16(&w_s[nb][kk][d4*4], Wc + (size_t)kk*DD + d4*4);
            }
            cp_commit();
            cp_wait1();
        } else {
            cp_wait0();
        }
        __syncthreads();

        int g = c / 3, kc = c % 3;
        const float (*X)[96] = (g == 1 || g == 4) ? h_s : a_s;
        const float (*Wt)[96] = w_s[c & 1];
        #pragma unroll
        for (int k2 = 0; k2 < 16; k2++) {
            float2 av[4];
            #pragma unroll
            for (int i = 0; i < 4; i++)
                av[i] = *(const float2*)&X[ty*4 + i][kc*32 + k2*2];
            #pragma unroll
            for (int kk = 0; kk < 2; kk++) {
                unsigned long long bp[3];
                #pragma unroll
                for (int q = 0; q < 3; q++)
                    bp[q] = *(const unsigned long long*)&Wt[k2*2 + kk][tx*6 + 2*q];
                #pragma unroll
                for (int i = 0; i < 4; i++) {
                    float a = kk ? av[i].y : av[i].x;
                    unsigned long long ap = pack2(a, a);
                    #pragma unroll
                    for (int q = 0; q < 3; q++) ffma2(acc[i][q], ap, bp[q]);
                }
            }
        }
        __syncthreads();

        if (c == 5) {
            #pragma unroll
            for (int i = 0; i < 4; i++)
                #pragma unroll
                for (int q = 0; q < 3; q++) {
                    float2 v = unpack2(acc[i][q]);
                    int cc = tx*6 + 2*q;
                    zr[i][q].x = sigmoidf_(v.x + bb[0*DD + cc]     + bb[1*DD + cc]);
                    zr[i][q].y = sigmoidf_(v.y + bb[0*DD + cc + 1] + bb[1*DD + cc + 1]);
                    acc[i][q] = 0ull;
                }
        } else if (c == 8) {
            #pragma unroll
            for (int i = 0; i < 4; i++)
                #pragma unroll
                for (int q = 0; q < 3; q++) {
                    hp[i][q] = unpack2(acc[i][q]);
                    acc[i][q] = 0ull;
                }
        } else if (c == 14) {
            #pragma unroll
            for (int i = 0; i < 4; i++)
                #pragma unroll
                for (int q = 0; q < 3; q++) {
                    float2 v = unpack2(acc[i][q]);
                    int cc = tx*6 + 2*q;
                    float2 hv = *(const float2*)&h_s[ty*4 + i][cc];
                    float r0 = sigmoidf_(v.x + bb[2*DD + cc]     + bb[3*DD + cc]);
                    float r1 = sigmoidf_(v.y + bb[2*DD + cc + 1] + bb[3*DD + cc + 1]);
                    *(float2*)&a_s[ty*4 + i][cc] = make_float2(r0*hv.x, r1*hv.y);
                    acc[i][q] = 0ull;
                }
        }
    }

    #pragma unroll
    for (int i = 0; i < 4; i++) {
        int m = m0 + ty*4 + i;
        float mkv = mask[m];
        #pragma unroll
        for (int q = 0; q < 3; q++) {
            float2 v = unpack2(acc[i][q]);
            int cc = tx*6 + 2*q;
            float2 hv = *(const float2*)&h_s[ty*4 + i][cc];
            float hh0 = fmaxf(mkv * (v.x + hp[i][q].x + bb[4*DD + cc]     + bb[5*DD + cc]),     0.f);
            float hh1 = fmaxf(mkv * (v.y + hp[i][q].y + bb[4*DD + cc + 1] + bb[5*DD + cc + 1]), 0.f);
            float o0 = hh0*zr[i][q].x + hv.x*(1.f - zr[i][q].x);
            float o1 = hh1*zr[i][q].y + hv.y*(1.f - zr[i][q].y);
            *(float2*)&g_h[br][m][cc] = make_float2(o0, o1);
        }
    }
}

// =========================================================================
//  f1 / f2 (unchanged)
// =========================================================================
__device__ __forceinline__ void mm96(const float* __restrict__ In, const float* __restrict__ W,
                                     int m0, int tid, unsigned long long acc[4][3])
{
    __shared__ __align__(16) float Xs[64][32];
    __shared__ __align__(16) float Ws[32][96];
    int tx = tid & 15, ty = tid >> 4;
    #pragma unroll 1
    for (int k0 = 0; k0 < DD; k0 += 32) {
        #pragma unroll
        for (int l = 0; l < 2; l++) {
            int e = tid + l*256;
            int r = e >> 3, k4 = e & 7;
            *(float4*)&Xs[r][k4*4] = *(const float4*)(In + (size_t)(m0 + r)*DD + k0 + k4*4);
        }
        #pragma unroll
        for (int l = 0; l < 3; l++) {
            int e = tid + l*256;
            int kk = e / 24, d4 = e % 24;
            *(float4*)&Ws[kk][d4*4] = *(const float4*)(W + (size_t)(k0 + kk)*DD + d4*4);
        }
        __syncthreads();
        step32_64(Xs, Ws, tx, ty, acc);
        __syncthreads();
    }
}

__device__ __forceinline__ void mm96pairL(const float* __restrict__ T0, const float* __restrict__ T1,
                                          const float* __restrict__ W, int m0, int tid,
                                          unsigned long long acc[4][3])
{
    __shared__ __align__(16) float Xs[64][32];
    __shared__ __align__(16) float Ws[32][96];
    int tx = tid & 15, ty = tid >> 4;
    #pragma unroll 1
    for (int k0 = 0; k0 < DD; k0 += 32) {
        #pragma unroll
        for (int l = 0; l < 2; l++) {
            int e = tid + l*256;
            int r = e >> 3, k4 = e & 7;
            size_t off = (size_t)(m0 + r)*DD + k0 + k4*4;
            float4 u = *(const float4*)(T0 + off);
            float4 v = *(const float4*)(T1 + off);
            float4 w;
            w.x = lrelu(u.x + v.x); w.y = lrelu(u.y + v.y);
            w.z = lrelu(u.z + v.z); w.w = lrelu(u.w + v.w);
            *(float4*)&Xs[r][k4*4] = w;
        }
        #pragma unroll
        for (int l = 0; l < 3; l++) {
            int e = tid + l*256;
            int kk = e / 24, d4 = e % 24;
            *(float4*)&Ws[kk][d4*4] = *(const float4*)(W + (size_t)(k0 + kk)*DD + d4*4);
        }
        __syncthreads();
        step32_64(Xs, Ws, tx, ty, acc);
        __syncthreads();
    }
}

__global__ __launch_bounds__(256) void f1_kernel(
    const float* __restrict__ Wii, const float* __restrict__ bii)
{
    int br = blockIdx.y;
    int m0 = blockIdx.x * 64;
    int tid = threadIdx.x, tx = tid & 15, ty = tid >> 4;
    unsigned long long acc[4][3] = {};
    mm96(&g_h[br][0][0], Wii + (size_t)br*DD*DD, m0, tid, acc);
    #pragma unroll
    for (int i = 0; i < 4; i++) {
        int m = m0 + ty*4 + i;
        #pragma unroll
        for (int q = 0; q < 3; q++) {
            float2 v = unpack2(acc[i][q]);
            int c = tx*6 + 2*q;
            *(float2*)&g_t[br][m][c] = make_float2(v.x + bii[br*DD + c],
                                                   v.y + bii[br*DD + c + 1]);
        }
    }
}

__global__ __launch_bounds__(256) void f2_kernel(
    const float* __restrict__ Watt, const float* __restrict__ batt, float* __restrict__ out)
{
    int m0 = blockIdx.x * 64;
    int tid = threadIdx.x, tx = tid & 15, ty = tid >> 4;
    unsigned long long acc[4][3] = {};
    #pragma unroll 1
    for (int j = 0; j < 3; j++) {
        const float* T0 = &g_t[j][0][0];
        const float* T1 = &g_t[(j + 1) % 3][0][0];
        mm96pairL(T0, T1, Watt + (size_t)j*DD*DD, m0, tid, acc);
    }
    #pragma unroll
    for (int i = 0; i < 4; i++) {
        int m = m0 + ty*4 + i;
        #pragma unroll
        for (int q = 0; q < 3; q++) {
            float2 v = unpack2(acc[i][q]);
            int c = tx*6 + 2*q;
            float b0 = batt[c]     + batt[DD + c]     + batt[2*DD + c];
            float b1 = batt[c + 1] + batt[DD + c + 1] + batt[2*DD + c + 1];
            *(float2*)&out[(size_t)m*DD + c] = make_float2(v.x + b0, v.y + b1);
        }
    }
}

// =========================================================================
//  launch
// =========================================================================
extern "C" void kernel_launch(void* const* d_in, const int* in_sizes, int n_in,
                              void* d_out, int out_size)
{
    const float* x     = (const float*)d_in[0];
    const float* adjA  = (const float*)d_in[1];
    const float* adjB  = (const float*)d_in[2];
    const float* adjC  = (const float*)d_in[3];
    const float* mask  = (const float*)d_in[4];
    const float* mask1 = (const float*)d_in[5];
    const float* mask2 = (const float*)d_in[6];
    const float* Wenc  = (const float*)d_in[7];
    const float* benc  = (const float*)d_in[8];
    const float* Wii   = (const float*)d_in[9];
    const float* bii   = (const float*)d_in[10];
    const float* Wgru  = (const float*)d_in[11];
    const float* bgru  = (const float*)d_in[12];
    const float* Watt  = (const float*)d_in[13];
    const float* batt  = (const float*)d_in[14];
    float* out = (float*)d_out;

    cudaFuncSetAttribute(gates_kernel, cudaFuncAttributeMaxDynamicSharedMemorySize, GATES_SMEM);

    conv_adj_kernel<<<dim3(NN*NN/(4*256), BB, 3), 256>>>(adjA, adjB, adjC);
    encode_kernel<<<dim3(MTOT/64, 3), 256>>>(x, Wenc, benc, mask, mask1, mask2);
    for (int s = 0; s < 2; s++) {
        conv_hT_kernel<<<dim3(MTOT/64, 3), 256>>>();
        msg_mma_kernel<<<dim3(NN/128, BB, 3), 128>>>();
        gates_kernel<<<dim3(MTOT/64, 3), 256, GATES_SMEM>>>(Wgru, bgru, mask, mask1, mask2);
    }
    f1_kernel<<<dim3(MTOT/64, 3), 256>>>(Wii, bii);
    f2_kernel<<<MTOT/64, 256>>>(Watt, batt, out);
}